// round 5
// baseline (speedup 1.0000x reference)
#include <cuda_runtime.h>
#include <cuda_bf16.h>

// SAN Subtraction: out[n,c,kk,p] = x[n,c,h,w] - reflectpad(x)[n,c,h+kh,w+kw]
// N=4, C=64, H=W=112, K=7, PAD=3, reflect. out (N,C,49,12544) fp32 = 630 MB writes.
// v5: 8 floats per thread; 256-bit stores (STG.E.256, sm_100+) and 256-bit
// center load; 4 aligned LDG.128 cover the 16-float neighbor span per kh;
// reflect edge fixups are register moves. Halves store instrs, cuts load ops 33%.

#define H 112
#define W 112
#define KS 7
#define PADV 3
#define HW (H * W)            // 12544
#define CC 64
#define NN 4
#define TPB 224               // threads; each owns 8 floats -> 16 rows/block

__device__ __forceinline__ int reflect_h(int j) {
    j = j < 0 ? -j : j;
    j = j >= H ? (2 * (H - 1) - j) : j;
    return j;
}

__device__ __forceinline__ void st_v8_cs(float* p, const float* v) {
    asm volatile("st.global.cs.v8.f32 [%0], {%1,%2,%3,%4,%5,%6,%7,%8};"
        :: "l"(p), "f"(v[0]), "f"(v[1]), "f"(v[2]), "f"(v[3]),
           "f"(v[4]), "f"(v[5]), "f"(v[6]), "f"(v[7]) : "memory");
}

__device__ __forceinline__ void ld_v8_nc(float* v, const float* p) {
    asm volatile("ld.global.nc.v8.f32 {%0,%1,%2,%3,%4,%5,%6,%7}, [%8];"
        : "=f"(v[0]), "=f"(v[1]), "=f"(v[2]), "=f"(v[3]),
          "=f"(v[4]), "=f"(v[5]), "=f"(v[6]), "=f"(v[7]) : "l"(p));
}

__global__ void __launch_bounds__(TPB) san_sub_kernel(
    const float* __restrict__ x, float* __restrict__ out)
{
    const int i8 = blockIdx.x * TPB + threadIdx.x;   // 8-float span idx, 0..1567
    const int h  = i8 / 14;                          // 14 spans per row
    const int w8 = (i8 - h * 14) << 3;               // 0,8,...,104
    const int plane = blockIdx.z * CC + blockIdx.y;

    const bool pL = (w8 != 0);
    const bool pR = (w8 != W - 8);

    const float* xp = x + (size_t)plane * HW;
    float* op = out + (size_t)plane * (KS * KS) * HW + ((size_t)i8 << 3);

    float ctr[8];
    ld_v8_nc(ctr, xp + ((size_t)i8 << 3));           // 32B-aligned

    #pragma unroll
    for (int kh = 0; kh < KS; ++kh) {
        const int rh = reflect_h(h + kh - PADV);
        const float* row = xp + rh * W;

        // v[j] = x[row, w8-4+j], j=0..15 (interior); edges fixed by reg moves
        float v[16];
        if (pL) *reinterpret_cast<float4*>(&v[0]) =
                    *reinterpret_cast<const float4*>(row + w8 - 4);
        *reinterpret_cast<float4*>(&v[4]) =
                    *reinterpret_cast<const float4*>(row + w8);
        *reinterpret_cast<float4*>(&v[8]) =
                    *reinterpret_cast<const float4*>(row + w8 + 4);
        if (pR) *reinterpret_cast<float4*>(&v[12]) =
                    *reinterpret_cast<const float4*>(row + w8 + 8);
        if (!pL) {            // w8==0: x[-3,-2,-1] -> x[3,2,1]
            v[1] = v[7]; v[2] = v[6]; v[3] = v[5];
        }
        if (!pR) {            // w8==104: x[112,113,114] -> x[110,109,108]
            v[12] = v[10]; v[13] = v[9]; v[14] = v[8];
        }

        #pragma unroll
        for (int kw = 0; kw < KS; ++kw) {
            float o[8];
            #pragma unroll
            for (int e = 0; e < 8; ++e)
                o[e] = ctr[e] - v[e + kw + 1];
            st_v8_cs(op + (size_t)(kh * KS + kw) * HW, o);
        }
    }
}

extern "C" void kernel_launch(void* const* d_in, const int* in_sizes, int n_in,
                              void* d_out, int out_size) {
    const float* x = (const float*)d_in[0];
    float* out = (float*)d_out;
    dim3 block(TPB, 1, 1);
    dim3 grid(HW / 8 / TPB, CC, NN);   // (7, 64, 4) = 1792 blocks
    san_sub_kernel<<<grid, block>>>(x, out);
}

// round 6
// speedup vs baseline: 1.0717x; 1.0717x over previous
#include <cuda_runtime.h>
#include <cuda_bf16.h>

// SAN Subtraction: out[n,c,kk,p] = x[n,c,h,w] - reflectpad(x)[n,c,h+kh,w+kw]
// N=4, C=64, H=W=112, K=7, PAD=3, reflect. out (N,C,49,12544) fp32 = 630 MB writes.
// v6 = R3 (best timed: linear warp mapping, kh/kw-interleaved 49-stream order,
// __stcs, occ>=60%) with the 10 scalar neighbor LDGs replaced by 3 aligned
// LDG.128 + register-move reflect fixups (L1 load wavefronts cut ~3x).
// DRAM% has been ~74% across 4 structurally different kernels -> at the
// practical HBM write ceiling; this round removes the last L1-side work.

#define H 112
#define W 112
#define KS 7
#define PADV 3
#define HW (H * W)            // 12544
#define CC 64
#define NN 4
#define W4N 28                // float4s per row
#define TPB 224               // 7 warps; 224 float4s/block; 14 blocks/plane

__device__ __forceinline__ int reflect_h(int j) {
    j = j < 0 ? -j : j;
    j = j >= H ? (2 * (H - 1) - j) : j;
    return j;
}

__global__ void __launch_bounds__(TPB, 6) san_sub_kernel(
    const float* __restrict__ x, float* __restrict__ out)
{
    const int i  = blockIdx.x * TPB + threadIdx.x;   // float4 index in plane
    const int h  = i / W4N;
    const int w4 = (i - h * W4N) << 2;               // 0,4,...,108
    const int plane = blockIdx.z * CC + blockIdx.y;  // n*64 + c

    const bool pL = (w4 != 0);
    const bool pR = (w4 != W - 4);

    const float* xp = x + (size_t)plane * HW;
    float* op = out + (size_t)plane * (KS * KS) * HW + ((size_t)i << 2);

    const float4 ctr = *reinterpret_cast<const float4*>(xp + ((size_t)i << 2));

    #pragma unroll
    for (int kh = 0; kh < KS; ++kh) {
        const int rh = reflect_h(h + kh - PADV);
        const float* row = xp + rh * W;

        // v[j] = x[row, w4-4+j], j=0..11 (interior); edges fixed by reg moves
        float v[12];
        if (pL) *reinterpret_cast<float4*>(&v[0]) =
                    *reinterpret_cast<const float4*>(row + w4 - 4);
        *reinterpret_cast<float4*>(&v[4]) =
                    *reinterpret_cast<const float4*>(row + w4);
        if (pR) *reinterpret_cast<float4*>(&v[8]) =
                    *reinterpret_cast<const float4*>(row + w4 + 4);
        if (!pL) {            // w4==0: x[-3,-2,-1] -> x[3,2,1]
            v[1] = v[7]; v[2] = v[6]; v[3] = v[5];
        }
        if (!pR) {            // w4==108: x[112,113,114] -> x[110,109,108]
            v[8] = v[6]; v[9] = v[5]; v[10] = v[4];
        }

        #pragma unroll
        for (int kw = 0; kw < KS; ++kw) {
            float4 o;
            o.x = ctr.x - v[kw + 1];
            o.y = ctr.y - v[kw + 2];
            o.z = ctr.z - v[kw + 3];
            o.w = ctr.w - v[kw + 4];
            __stcs(reinterpret_cast<float4*>(op + (size_t)(kh * KS + kw) * HW), o);
        }
    }
}

extern "C" void kernel_launch(void* const* d_in, const int* in_sizes, int n_in,
                              void* d_out, int out_size) {
    const float* x = (const float*)d_in[0];
    float* out = (float*)d_out;
    dim3 block(TPB, 1, 1);
    dim3 grid(HW / 4 / TPB, CC, NN);   // (14, 64, 4) = 3584 blocks
    san_sub_kernel<<<grid, block>>>(x, out);
}